// round 17
// baseline (speedup 1.0000x reference)
#include <cuda_runtime.h>
#include <cstdint>

#define HH 512
#define WW 512
#define MAXB 16
#define MAXBN 512          // max B*N slabs
#define NCH 4              // H-chunks per slab
#define CHROWS (HH / NCH)  // 128 rows per chunk

// Scratch (device globals — zero-initialized at module load; no allocation).
__device__ int    g_xmin [MAXB * HH];
__device__ int    g_xmax [MAXB * HH];
__device__ float4 g_theta[MAXB];                 // {sl_l, ic_l, sl_r, ic_r}
__device__ float  g_colp [MAXBN][NCH][WW];       // per-chunk column sums
__device__ float  g_part [MAXBN][NCH][2];        // per-chunk {inst, vert}
__device__ int    g_cnt  [MAXBN];                // size-chunk combine election

// ---------------------------------------------------------------------------
// Kernel A: per-row min/max positive column of seg channel 1. Pure stream,
// explicit 8-deep load batch per lane. Grid = B*32, 512 thr, warp owns a row.
// (Exact R12 body — measured best at 7.68us; overhead-bound, not fixable.)
// ---------------------------------------------------------------------------
__global__ void __launch_bounds__(512) minmax_kernel(const float* __restrict__ seg)
{
    const int b    = blockIdx.x >> 5;
    const int blk  = blockIdx.x & 31;
    const int lane = threadIdx.x & 31;
    const int warp = threadIdx.x >> 5;

    const int h = blk * 16 + warp;
    const float4* row = (const float4*)(seg + (size_t)b * HH * WW * 2
                                            + (size_t)h * WW * 2);

    const float4 v0 = row[lane +   0];
    const float4 v1 = row[lane +  32];
    const float4 v2 = row[lane +  64];
    const float4 v3 = row[lane +  96];
    const float4 v4 = row[lane + 128];
    const float4 v5 = row[lane + 160];
    const float4 v6 = row[lane + 192];
    const float4 v7 = row[lane + 224];

    int mn = WW, mx = -1;
    #define MM_ACC(v, base)                                                    \
        do {                                                                   \
            const int p0 = 2 * (lane + (base));                                \
            if ((v).y > 0.0f) { mn = min(mn, p0);     mx = max(mx, p0); }      \
            if ((v).w > 0.0f) { mn = min(mn, p0 + 1); mx = max(mx, p0 + 1); }  \
        } while (0)
    MM_ACC(v0,   0); MM_ACC(v1,  32); MM_ACC(v2,  64); MM_ACC(v3,  96);
    MM_ACC(v4, 128); MM_ACC(v5, 160); MM_ACC(v6, 192); MM_ACC(v7, 224);
    #undef MM_ACC

    #pragma unroll
    for (int o = 16; o; o >>= 1) {
        mn = min(mn, __shfl_down_sync(0xffffffffu, mn, o));
        mx = max(mx, __shfl_down_sync(0xffffffffu, mx, o));
    }
    if (lane == 0) {
        g_xmin[b * HH + h] = mn;
        g_xmax[b * HH + h] = mx;
    }
    __threadfence();
    cudaTriggerProgrammaticLaunchCompletion();
}

// ---------------------------------------------------------------------------
// Kernel B: trimmed weighted-LS fit -> theta per image. Grid = B, tiny.
// PDL-dependent on kernel A. (Exact R12 body.)
// ---------------------------------------------------------------------------
__global__ void __launch_bounds__(512) fit_kernel()
{
    const int b    = blockIdx.x;
    const int tid  = threadIdx.x;
    const int lane = tid & 31;
    const int warp = tid >> 5;

    __shared__ int   wtot[16];
    __shared__ float acc[7];
    if (tid < 7) acc[tid] = 0.0f;

    cudaGridDependencySynchronize();          // wait for minmax grid

    const int xmin_i = g_xmin[b * HH + tid];
    const int xmax_i = g_xmax[b * HH + tid];
    const int valid  = (xmax_i >= 0 && xmin_i != xmax_i) ? 1 : 0;

    unsigned bal = __ballot_sync(0xffffffffu, valid);
    int pre = __popc(bal & ((1u << lane) - 1u));
    if (lane == 0) wtot[warp] = __popc(bal);
    __syncthreads();

    int off = 0, nvalid = 0;
    #pragma unroll
    for (int i = 0; i < 16; i++) {
        int t = wtot[i];
        nvalid += t;
        if (i < warp) off += t;
    }
    const int rank = off + pre;

    int drop = (int)((float)nvalid * 0.15f);   // trunc, matches astype(int32)
    if (drop < 1) drop = 1;
    const int keep = valid && (rank >= drop) && (rank < nvalid - drop);

    const float w  = keep ? 1.0f : 0.0f;
    const float y  = (float)tid;
    const float xl = (float)xmin_i;
    const float xr = (float)xmax_i;

    float s0 = w, s1 = w * y, s2 = w * y * y;
    float s3 = w * xl, s4 = w * y * xl;
    float s5 = w * xr, s6 = w * y * xr;

    #pragma unroll
    for (int o = 16; o; o >>= 1) {
        s0 += __shfl_down_sync(0xffffffffu, s0, o);
        s1 += __shfl_down_sync(0xffffffffu, s1, o);
        s2 += __shfl_down_sync(0xffffffffu, s2, o);
        s3 += __shfl_down_sync(0xffffffffu, s3, o);
        s4 += __shfl_down_sync(0xffffffffu, s4, o);
        s5 += __shfl_down_sync(0xffffffffu, s5, o);
        s6 += __shfl_down_sync(0xffffffffu, s6, o);
    }
    if (lane == 0) {
        atomicAdd(&acc[0], s0); atomicAdd(&acc[1], s1); atomicAdd(&acc[2], s2);
        atomicAdd(&acc[3], s3); atomicAdd(&acc[4], s4);
        atomicAdd(&acc[5], s5); atomicAdd(&acc[6], s6);
    }
    __syncthreads();

    if (tid == 0) {
        const float Sw  = acc[0], Sy  = acc[1], Syy = acc[2];
        const float Sxl = acc[3], Sxyl = acc[4];
        const float Sxr = acc[5], Sxyr = acc[6];

        const float det  = Syy * Sw - Sy * Sy;
        const float safe = (det > 0.0f) ? det : 1.0f;

        float sl_l = (Sw * Sxyl - Sy * Sxl) / safe;
        float ic_l = (-Sy * Sxyl + Syy * Sxl) / safe;
        float sl_r = (Sw * Sxyr - Sy * Sxr) / safe;
        float ic_r = (-Sy * Sxyr + Syy * Sxr) / safe;
        if (!(det > 0.0f)) { sl_l = ic_l = sl_r = ic_r = 0.0f; }

        g_theta[b] = make_float4(sl_l, ic_l, sl_r, ic_r);
        __threadfence();
    }
    __syncthreads();
    cudaTriggerProgrammaticLaunchCompletion();
}

// ---------------------------------------------------------------------------
// Kernel C: one block per (bn, chunk); chunk = 128 rows. 256 threads =
// 4 row-groups x 64 col-threads; thread (g, c) loads TWO float4 per
// iteration (columns 4c..4c+3 and 256+4c..256+4c+3) into separate
// accumulators -> 2 independent in-flight loads/thread, and 256-thr blocks
// let ~5 CTAs reside per SM -> ~40KB in flight > 32KB BW-delay product.
// Rows: h = g + 4k, k = 0..31 (same mapping as before).
// ---------------------------------------------------------------------------
__global__ void __launch_bounds__(256) size_kernel(const float* __restrict__ pad,
                                                   float* __restrict__ out,
                                                   int N)
{
    const int bn   = blockIdx.x >> 2;
    const int ch   = blockIdx.x & 3;
    const int b    = bn / N;
    const int tid  = threadIdx.x;
    const int lane = tid & 31;
    const int warp = tid >> 5;
    const int g    = tid >> 6;        // row group 0..3
    const int c    = tid & 63;        // column pair: cols 4c.. and 256+4c..
    const int h0   = ch * CHROWS;     // first global row of this chunk

    __shared__ float    su [CHROWS];
    __shared__ float    su2[CHROWS];
    __shared__ float    scol[WW];
    __shared__ unsigned grpmask[4];
    __shared__ float    sred[8];
    __shared__ float    svert[4];

    // data-independent prologue (overlaps predecessor execution under PDL)
    scol[tid]       = 0.0f;
    scol[tid + 256] = 0.0f;
    if (tid < 4) grpmask[tid] = 0u;
    const float4* p = (const float4*)(pad + (size_t)bn * HH * WW
                                          + (size_t)h0 * WW);

    cudaGridDependencySynchronize();          // wait for fit grid

    if (tid < CHROWS) {
        const float4 th = g_theta[b];         // {sl_l, ic_l, sl_r, ic_r}
        const float y = (float)(h0 + tid);
        float width = (y * th.z + th.w) - (y * th.x + th.y);
        width = fmaxf(width, 1.0f);
        const float u = 3.25f / width;
        su [tid] = u;
        su2[tid] = u * u;
    }
    __syncthreads();

    float4 acc_a = make_float4(0.f, 0.f, 0.f, 0.f);
    float4 acc_b = make_float4(0.f, 0.f, 0.f, 0.f);
    float  inst  = 0.0f;
    unsigned lm  = 0u;

    #pragma unroll 8
    for (int k = 0; k < 32; k++) {
        const int h = g + 4 * k;      // local row
        const float4 va = p[(size_t)h * (WW / 4) + c];
        const float4 vb = p[(size_t)h * (WW / 4) + c + 64];
        const float u1 = su[h], u2 = su2[h];
        acc_a.x = fmaf(u1, va.x, acc_a.x);
        acc_a.y = fmaf(u1, va.y, acc_a.y);
        acc_a.z = fmaf(u1, va.z, acc_a.z);
        acc_a.w = fmaf(u1, va.w, acc_a.w);
        acc_b.x = fmaf(u1, vb.x, acc_b.x);
        acc_b.y = fmaf(u1, vb.y, acc_b.y);
        acc_b.z = fmaf(u1, vb.z, acc_b.z);
        acc_b.w = fmaf(u1, vb.w, acc_b.w);
        inst = fmaf(u2, ((va.x + va.y) + (va.z + va.w))
                      + ((vb.x + vb.y) + (vb.z + vb.w)), inst);
        if (va.x > 0.5f || va.y > 0.5f || va.z > 0.5f || va.w > 0.5f ||
            vb.x > 0.5f || vb.y > 0.5f || vb.z > 0.5f || vb.w > 0.5f)
            lm |= (1u << k);
    }

    // row-occupied bits: OR across the 2 warps of each group
    {
        unsigned m = __reduce_or_sync(0xffffffffu, lm);
        if (lane == 0 && m) atomicOr(&grpmask[g], m);
    }

    // per-column sums: combine 4 row-groups via shared atomics
    atomicAdd(&scol[4 * c + 0], acc_a.x);
    atomicAdd(&scol[4 * c + 1], acc_a.y);
    atomicAdd(&scol[4 * c + 2], acc_a.z);
    atomicAdd(&scol[4 * c + 3], acc_a.w);
    atomicAdd(&scol[256 + 4 * c + 0], acc_b.x);
    atomicAdd(&scol[256 + 4 * c + 1], acc_b.y);
    atomicAdd(&scol[256 + 4 * c + 2], acc_b.z);
    atomicAdd(&scol[256 + 4 * c + 3], acc_b.w);

    // instance partial (block sum, 8 warps)
    float s = inst;
    #pragma unroll
    for (int o = 16; o; o >>= 1) s += __shfl_down_sync(0xffffffffu, s, o);
    if (lane == 0) sred[warp] = s;
    __syncthreads();

    // vertical partial: local row r handled by group r&3, iteration r>>2
    float vv = 0.0f;
    if (tid < CHROWS) {
        const unsigned bit = (grpmask[tid & 3] >> (tid >> 2)) & 1u;
        vv = bit ? su[tid] : 0.0f;
    }
    #pragma unroll
    for (int o = 16; o; o >>= 1) vv += __shfl_down_sync(0xffffffffu, vv, o);
    if (lane == 0 && warp < 4) svert[warp] = vv;
    __syncthreads();

    if (tid == 0) {
        float ti = 0.0f;
        #pragma unroll
        for (int i = 0; i < 8; i++) ti += sred[i];
        float tv = (svert[0] + svert[1]) + (svert[2] + svert[3]);
        g_part[bn][ch][0] = ti;
        g_part[bn][ch][1] = tv;
    }

    // column partials to scratch (coalesced, 2 per thread)
    g_colp[bn][ch][tid]       = scol[tid];
    g_colp[bn][ch][tid + 256] = scol[tid + 256];
    __threadfence();

    // elect last chunk-block of this slab to combine
    __shared__ int isLastC;
    __syncthreads();
    if (tid == 0) isLastC = (atomicAdd(&g_cnt[bn], 1) == NCH - 1);
    __syncthreads();
    if (!isLastC) return;
    __threadfence();

    // horizontal: per-column sum over chunks (fixed order), then block max
    float ca = __ldcg(&g_colp[bn][0][tid]);
    ca += __ldcg(&g_colp[bn][1][tid]);
    ca += __ldcg(&g_colp[bn][2][tid]);
    ca += __ldcg(&g_colp[bn][3][tid]);
    float cb = __ldcg(&g_colp[bn][0][tid + 256]);
    cb += __ldcg(&g_colp[bn][1][tid + 256]);
    cb += __ldcg(&g_colp[bn][2][tid + 256]);
    cb += __ldcg(&g_colp[bn][3][tid + 256]);

    float m = fmaxf(ca, cb);
    #pragma unroll
    for (int o = 16; o; o >>= 1) m = fmaxf(m, __shfl_down_sync(0xffffffffu, m, o));
    if (lane == 0) sred[warp] = m;
    __syncthreads();

    if (tid == 0) {
        float hmax = sred[0];
        #pragma unroll
        for (int i = 1; i < 8; i++) hmax = fmaxf(hmax, sred[i]);

        float ti = 0.0f, tv = 0.0f;
        #pragma unroll
        for (int i = 0; i < NCH; i++) {
            ti += __ldcg(&g_part[bn][i][0]);
            tv += __ldcg(&g_part[bn][i][1]);
        }
        out[bn * 3 + 0] = ti;
        out[bn * 3 + 1] = hmax;
        out[bn * 3 + 2] = tv;

        g_cnt[bn] = 0;               // reset for the next graph replay
    }
}

// ---------------------------------------------------------------------------
extern "C" void kernel_launch(void* const* d_in, const int* in_sizes, int n_in,
                              void* d_out, int out_size)
{
    const float* seg = (const float*)d_in[0];   // [B, H, W, 2]
    const float* pad = (const float*)d_in[1];   // [B, N, H, W]
    float* out = (float*)d_out;                 // [B, N, 3]

    const int B = in_sizes[0] / (HH * WW * 2);
    const int N = in_sizes[1] / (B * HH * WW);

    minmax_kernel<<<B * 32, 512>>>(seg);

    cudaLaunchAttribute attr[1];
    attr[0].id = cudaLaunchAttributeProgrammaticStreamSerialization;
    attr[0].val.programmaticStreamSerializationAllowed = 1;

    cudaLaunchConfig_t cfgB = {};
    cfgB.gridDim  = dim3(B, 1, 1);
    cfgB.blockDim = dim3(512, 1, 1);
    cfgB.attrs    = attr;
    cfgB.numAttrs = 1;
    cudaLaunchKernelEx(&cfgB, fit_kernel);

    cudaLaunchConfig_t cfgC = {};
    cfgC.gridDim  = dim3(B * N * NCH, 1, 1);
    cfgC.blockDim = dim3(256, 1, 1);
    cfgC.attrs    = attr;
    cfgC.numAttrs = 1;
    cudaLaunchKernelEx(&cfgC, size_kernel, (const float*)pad, (float*)out, (int)N);
}